// round 9
// baseline (speedup 1.0000x reference)
#include <cuda_runtime.h>

#define N_NODES 100000
#define N_EDGES 3200000

// ---- persistent device scratch (no allocations allowed) ----
__device__ int   g_deg [N_NODES];
__device__ float g_dinv[N_NODES];
__device__ float g_xn  [N_NODES * 4];   // x * dinv  (src-normalized features)
__device__ float g_agg [N_NODES * 4];   // layer-1 accumulator, init = xn (self loop)
__device__ float g_tn  [N_NODES * 2];   // t * dinv  (src-normalized layer-2 features)

// Weights staged into constant memory each call (broadcast LDC instead of LDG).
// Layout: W1[64] | b1[16] | W2[32] | b2[2]
__constant__ float c_W1[64];
__constant__ float c_b1[16];
__constant__ float c_W2[32];
__constant__ float c_b2[2];

// Vectorized no-return global reductions (one L2 message per 2/4 floats).
__device__ __forceinline__ void red_add_v4(float* p, float a, float b, float c, float d) {
    asm volatile("red.global.add.v4.f32 [%0], {%1,%2,%3,%4};"
                 :: "l"(p), "f"(a), "f"(b), "f"(c), "f"(d) : "memory");
}
__device__ __forceinline__ void red_add_v2(float* p, float a, float b) {
    asm volatile("red.global.add.v2.f32 [%0], {%1,%2};"
                 :: "l"(p), "f"(a), "f"(b) : "memory");
}
__device__ __forceinline__ void red_add_u32(int* p) {
    asm volatile("red.global.add.u32 [%0], 1;" :: "l"(p) : "memory");
}

// K1: degree of dst endpoints (4 edges / thread, int4-coalesced)
__global__ void k_deg(const int* __restrict__ dst) {
    int i = blockIdx.x * blockDim.x + threadIdx.x;
    if (i < N_EDGES / 4) {
        int4 d = reinterpret_cast<const int4*>(dst)[i];
        red_add_u32(&g_deg[d.x]);
        red_add_u32(&g_deg[d.y]);
        red_add_u32(&g_deg[d.z]);
        red_add_u32(&g_deg[d.w]);
    }
}

// K2: dinv = rsqrt(deg+1);  xn = x*dinv;  agg init = xn (layer-1 self loop)
__global__ void k_dinv_xn(const float* __restrict__ x) {
    int i = blockIdx.x * blockDim.x + threadIdx.x;
    if (i >= N_NODES) return;
    float di = rsqrtf((float)(g_deg[i] + 1));
    g_dinv[i] = di;
    float4 xv = reinterpret_cast<const float4*>(x)[i];
    float4 xn = make_float4(xv.x * di, xv.y * di, xv.z * di, xv.w * di);
    reinterpret_cast<float4*>(g_xn)[i]  = xn;
    reinterpret_cast<float4*>(g_agg)[i] = xn;
}

// K3: layer-1 edges: agg[dst] += xn[src]  (dst factor deferred)
__global__ void k_l1_edges(const int* __restrict__ src, const int* __restrict__ dst) {
    int i = blockIdx.x * blockDim.x + threadIdx.x;
    if (i >= N_EDGES / 4) return;
    int4 s = reinterpret_cast<const int4*>(src)[i];
    int4 d = reinterpret_cast<const int4*>(dst)[i];
    const float4* xv = reinterpret_cast<const float4*>(g_xn);

    float4 v0 = xv[s.x];
    float4 v1 = xv[s.y];
    float4 v2 = xv[s.z];
    float4 v3 = xv[s.w];
    red_add_v4(&g_agg[4 * d.x], v0.x, v0.y, v0.z, v0.w);
    red_add_v4(&g_agg[4 * d.y], v1.x, v1.y, v1.z, v1.w);
    red_add_v4(&g_agg[4 * d.z], v2.x, v2.y, v2.z, v2.w);
    red_add_v4(&g_agg[4 * d.w], v3.x, v3.y, v3.z, v3.w);
}

// K4: per-node transform (weights from constant memory).
//   a = dinv*agg;  h = relu(a@W1+b1);  t = h@W2;  tn = t*dinv;
//   out init = tn (layer-2 self loop pre-dst-scale)
__global__ void k_xform(float* __restrict__ out) {
    int v = blockIdx.x * blockDim.x + threadIdx.x;
    if (v >= N_NODES) return;
    float di = g_dinv[v];
    float4 ag = reinterpret_cast<const float4*>(g_agg)[v];
    float a0 = ag.x * di;
    float a1 = ag.y * di;
    float a2 = ag.z * di;
    float a3 = ag.w * di;

    float t0 = 0.f, t1 = 0.f;
    #pragma unroll
    for (int j = 0; j < 16; j++) {
        float h = fmaf(a0, c_W1[j],
                  fmaf(a1, c_W1[16 + j],
                  fmaf(a2, c_W1[32 + j],
                  fmaf(a3, c_W1[48 + j], c_b1[j]))));
        h = fmaxf(h, 0.f);
        t0 = fmaf(h, c_W2[2 * j],     t0);
        t1 = fmaf(h, c_W2[2 * j + 1], t1);
    }
    float tn0 = t0 * di, tn1 = t1 * di;
    reinterpret_cast<float2*>(g_tn)[v] = make_float2(tn0, tn1);
    reinterpret_cast<float2*>(out)[v]  = make_float2(tn0, tn1);  // self-loop init
}

// K5: layer-2 edges: out[dst] += tn[src]  (dst factor deferred)
__global__ void k_l2_edges(const int* __restrict__ src, const int* __restrict__ dst,
                           float* __restrict__ out) {
    int i = blockIdx.x * blockDim.x + threadIdx.x;
    if (i >= N_EDGES / 4) return;
    int4 s = reinterpret_cast<const int4*>(src)[i];
    int4 d = reinterpret_cast<const int4*>(dst)[i];
    const float2* tv = reinterpret_cast<const float2*>(g_tn);

    float2 t0 = tv[s.x];
    float2 t1 = tv[s.y];
    float2 t2 = tv[s.z];
    float2 t3 = tv[s.w];
    red_add_v2(&out[2 * d.x], t0.x, t0.y);
    red_add_v2(&out[2 * d.y], t1.x, t1.y);
    red_add_v2(&out[2 * d.z], t2.x, t2.y);
    red_add_v2(&out[2 * d.w], t3.x, t3.y);
}

// K6: apply deferred dst factor + bias:  out = out*dinv + b2 (constants)
__global__ void k_finish(float* __restrict__ out) {
    int v = blockIdx.x * blockDim.x + threadIdx.x;
    if (v >= N_NODES) return;
    float di = g_dinv[v];
    float2 o = reinterpret_cast<float2*>(out)[v];
    reinterpret_cast<float2*>(out)[v] =
        make_float2(fmaf(o.x, di, c_b2[0]), fmaf(o.y, di, c_b2[1]));
}

extern "C" void kernel_launch(void* const* d_in, const int* in_sizes, int n_in,
                              void* d_out, int out_size) {
    const float* x   = (const float*)d_in[0];     // [N, 4]
    const int*   ei  = (const int*)  d_in[1];     // [2, E]
    const float* W1  = (const float*)d_in[2];     // [4, 16]
    const float* b1  = (const float*)d_in[3];     // [16]
    const float* W2  = (const float*)d_in[4];     // [16, 2]
    const float* b2  = (const float*)d_in[5];     // [2]
    float* out = (float*)d_out;                   // [N, 2]

    const int* src = ei;
    const int* dst = ei + N_EDGES;

    const int TB = 256;
    int nodeBlocks = (N_NODES + TB - 1) / TB;
    int edgeBlocks = (N_EDGES / 4 + TB - 1) / TB;

    // Stage weights into constant memory (tiny async D2D copies; graph-legal).
    cudaMemcpyToSymbolAsync(c_W1, W1, 64 * sizeof(float), 0, cudaMemcpyDeviceToDevice);
    cudaMemcpyToSymbolAsync(c_b1, b1, 16 * sizeof(float), 0, cudaMemcpyDeviceToDevice);
    cudaMemcpyToSymbolAsync(c_W2, W2, 32 * sizeof(float), 0, cudaMemcpyDeviceToDevice);
    cudaMemcpyToSymbolAsync(c_b2, b2,  2 * sizeof(float), 0, cudaMemcpyDeviceToDevice);

    // Zero only the degree accumulator (single small DMA memset node).
    void* degp = nullptr;
    cudaGetSymbolAddress(&degp, g_deg);
    cudaMemsetAsync(degp, 0, N_NODES * sizeof(int));

    k_deg     <<<edgeBlocks, TB>>>(dst);
    k_dinv_xn <<<nodeBlocks, TB>>>(x);
    k_l1_edges<<<edgeBlocks, TB>>>(src, dst);
    k_xform   <<<nodeBlocks, TB>>>(out);
    k_l2_edges<<<edgeBlocks, TB>>>(src, dst, out);
    k_finish  <<<nodeBlocks, TB>>>(out);
}

// round 10
// speedup vs baseline: 1.0721x; 1.0721x over previous
#include <cuda_runtime.h>

#define N_NODES 100000
#define N_EDGES 3200000

// ---- persistent device scratch (no allocations allowed) ----
// g_deg is zero-initialized at module load; k_finish re-zeroes it every call,
// maintaining the "deg == 0 at entry" invariant without a memset graph node.
__device__ int   g_deg [N_NODES];
__device__ float g_dinv[N_NODES];
__device__ float g_xn  [N_NODES * 4];   // x * dinv  (src-normalized features)
__device__ float g_agg [N_NODES * 4];   // layer-1 accumulator, init = xn (self loop)
__device__ float g_tn  [N_NODES * 2];   // t * dinv  (src-normalized layer-2 features)

// Vectorized no-return global reductions (one L2 message per 2/4 floats).
__device__ __forceinline__ void red_add_v4(float* p, float a, float b, float c, float d) {
    asm volatile("red.global.add.v4.f32 [%0], {%1,%2,%3,%4};"
                 :: "l"(p), "f"(a), "f"(b), "f"(c), "f"(d) : "memory");
}
__device__ __forceinline__ void red_add_v2(float* p, float a, float b) {
    asm volatile("red.global.add.v2.f32 [%0], {%1,%2};"
                 :: "l"(p), "f"(a), "f"(b) : "memory");
}
__device__ __forceinline__ void red_add_u32(int* p) {
    asm volatile("red.global.add.u32 [%0], 1;" :: "l"(p) : "memory");
}

// K1: degree of dst endpoints (4 edges / thread, int4-coalesced)
__global__ void k_deg(const int* __restrict__ dst) {
    int i = blockIdx.x * blockDim.x + threadIdx.x;
    if (i < N_EDGES / 4) {
        int4 d = reinterpret_cast<const int4*>(dst)[i];
        red_add_u32(&g_deg[d.x]);
        red_add_u32(&g_deg[d.y]);
        red_add_u32(&g_deg[d.z]);
        red_add_u32(&g_deg[d.w]);
    }
}

// K2: dinv = rsqrt(deg+1);  xn = x*dinv;  agg init = xn (layer-1 self loop)
__global__ void k_dinv_xn(const float* __restrict__ x) {
    int i = blockIdx.x * blockDim.x + threadIdx.x;
    if (i >= N_NODES) return;
    float di = rsqrtf((float)(g_deg[i] + 1));
    g_dinv[i] = di;
    float4 xv = reinterpret_cast<const float4*>(x)[i];
    float4 xn = make_float4(xv.x * di, xv.y * di, xv.z * di, xv.w * di);
    reinterpret_cast<float4*>(g_xn)[i]  = xn;
    reinterpret_cast<float4*>(g_agg)[i] = xn;
}

// K3: layer-1 edges: agg[dst] += xn[src]  (dst factor deferred)
__global__ void k_l1_edges(const int* __restrict__ src, const int* __restrict__ dst) {
    int i = blockIdx.x * blockDim.x + threadIdx.x;
    if (i >= N_EDGES / 4) return;
    int4 s = reinterpret_cast<const int4*>(src)[i];
    int4 d = reinterpret_cast<const int4*>(dst)[i];
    const float4* xv = reinterpret_cast<const float4*>(g_xn);

    float4 v0 = xv[s.x];
    float4 v1 = xv[s.y];
    float4 v2 = xv[s.z];
    float4 v3 = xv[s.w];
    red_add_v4(&g_agg[4 * d.x], v0.x, v0.y, v0.z, v0.w);
    red_add_v4(&g_agg[4 * d.y], v1.x, v1.y, v1.z, v1.w);
    red_add_v4(&g_agg[4 * d.z], v2.x, v2.y, v2.z, v2.w);
    red_add_v4(&g_agg[4 * d.w], v3.x, v3.y, v3.z, v3.w);
}

// K4: per-node transform.
//   a = dinv*agg  (agg already contains self loop);  h = relu(a@W1+b1);
//   t = h@W2;  tn = t*dinv;  out init = tn (layer-2 self loop pre-dst-scale)
__global__ void k_xform(const float* __restrict__ W1, const float* __restrict__ b1,
                        const float* __restrict__ W2,
                        float* __restrict__ out) {
    int v = blockIdx.x * blockDim.x + threadIdx.x;
    if (v >= N_NODES) return;
    float di = g_dinv[v];
    float4 ag = reinterpret_cast<const float4*>(g_agg)[v];
    float a0 = ag.x * di;
    float a1 = ag.y * di;
    float a2 = ag.z * di;
    float a3 = ag.w * di;

    float t0 = 0.f, t1 = 0.f;
    #pragma unroll
    for (int j = 0; j < 16; j++) {
        float h = a0 * W1[j] + a1 * W1[16 + j] + a2 * W1[32 + j] + a3 * W1[48 + j] + b1[j];
        h = fmaxf(h, 0.f);
        t0 += h * W2[2 * j];
        t1 += h * W2[2 * j + 1];
    }
    float tn0 = t0 * di, tn1 = t1 * di;
    reinterpret_cast<float2*>(g_tn)[v] = make_float2(tn0, tn1);
    reinterpret_cast<float2*>(out)[v]  = make_float2(tn0, tn1);  // self-loop init
}

// K5: layer-2 edges: out[dst] += tn[src]  (dst factor deferred)
__global__ void k_l2_edges(const int* __restrict__ src, const int* __restrict__ dst,
                           float* __restrict__ out) {
    int i = blockIdx.x * blockDim.x + threadIdx.x;
    if (i >= N_EDGES / 4) return;
    int4 s = reinterpret_cast<const int4*>(src)[i];
    int4 d = reinterpret_cast<const int4*>(dst)[i];
    const float2* tv = reinterpret_cast<const float2*>(g_tn);

    float2 t0 = tv[s.x];
    float2 t1 = tv[s.y];
    float2 t2 = tv[s.z];
    float2 t3 = tv[s.w];
    red_add_v2(&out[2 * d.x], t0.x, t0.y);
    red_add_v2(&out[2 * d.y], t1.x, t1.y);
    red_add_v2(&out[2 * d.z], t2.x, t2.y);
    red_add_v2(&out[2 * d.w], t3.x, t3.y);
}

// K6: apply deferred dst factor + bias:  out = out*dinv + b2.
//     Also re-zero g_deg for the next call (replaces the memset graph node).
__global__ void k_finish(float* __restrict__ out, const float* __restrict__ b2) {
    int v = blockIdx.x * blockDim.x + threadIdx.x;
    if (v >= N_NODES) return;
    float di = g_dinv[v];
    float2 o = reinterpret_cast<float2*>(out)[v];
    reinterpret_cast<float2*>(out)[v] =
        make_float2(o.x * di + b2[0], o.y * di + b2[1]);
    g_deg[v] = 0;
}

extern "C" void kernel_launch(void* const* d_in, const int* in_sizes, int n_in,
                              void* d_out, int out_size) {
    const float* x   = (const float*)d_in[0];     // [N, 4]
    const int*   ei  = (const int*)  d_in[1];     // [2, E]
    const float* W1  = (const float*)d_in[2];     // [4, 16]
    const float* b1  = (const float*)d_in[3];     // [16]
    const float* W2  = (const float*)d_in[4];     // [16, 2]
    const float* b2  = (const float*)d_in[5];     // [2]
    float* out = (float*)d_out;                   // [N, 2]

    const int* src = ei;
    const int* dst = ei + N_EDGES;

    const int TB = 256;
    int nodeBlocks = (N_NODES + TB - 1) / TB;
    int edgeBlocks = (N_EDGES / 4 + TB - 1) / TB;

    k_deg     <<<edgeBlocks, TB>>>(dst);
    k_dinv_xn <<<nodeBlocks, TB>>>(x);
    k_l1_edges<<<edgeBlocks, TB>>>(src, dst);
    k_xform   <<<nodeBlocks, TB>>>(W1, b1, W2, out);
    k_l2_edges<<<edgeBlocks, TB>>>(src, dst, out);
    k_finish  <<<nodeBlocks, TB>>>(out, b2);
}

// round 11
// speedup vs baseline: 1.0982x; 1.0244x over previous
#include <cuda_runtime.h>

#define N_NODES 100000
#define N_EDGES 3200000

// ---- persistent device scratch (no allocations allowed) ----
// g_deg is zero-initialized at module load; k_finish re-zeroes it every call.
__device__ int   g_deg [N_NODES];
__device__ float g_dinv[N_NODES];
__device__ float g_xn  [N_NODES * 4];   // x * dinv  (src-normalized features)
__device__ float g_agg [N_NODES * 4];   // layer-1 accumulator, init = xn (self loop)
__device__ float g_tn  [N_NODES * 2];   // t * dinv  (src-normalized layer-2 features)

// Vectorized no-return global reductions (one L2 message per 2/4 floats).
__device__ __forceinline__ void red_add_v4(float* p, float a, float b, float c, float d) {
    asm volatile("red.global.add.v4.f32 [%0], {%1,%2,%3,%4};"
                 :: "l"(p), "f"(a), "f"(b), "f"(c), "f"(d) : "memory");
}
__device__ __forceinline__ void red_add_v2(float* p, float a, float b) {
    asm volatile("red.global.add.v2.f32 [%0], {%1,%2};"
                 :: "l"(p), "f"(a), "f"(b) : "memory");
}
__device__ __forceinline__ void red_add_u32(int* p) {
    asm volatile("red.global.add.u32 [%0], 1;" :: "l"(p) : "memory");
}

// K1: degree of dst endpoints. Independent load of dst indices first, then
// grid-dep sync (orders against previous replay's k_finish zeroing g_deg).
__global__ void k_deg(const int* __restrict__ dst) {
    int i = blockIdx.x * blockDim.x + threadIdx.x;
    if (i < N_EDGES / 4) {
        int4 d = reinterpret_cast<const int4*>(dst)[i];
        cudaGridDependencySynchronize();
        red_add_u32(&g_deg[d.x]);
        red_add_u32(&g_deg[d.y]);
        red_add_u32(&g_deg[d.z]);
        red_add_u32(&g_deg[d.w]);
    } else {
        cudaGridDependencySynchronize();
    }
}

// K2: dinv = rsqrt(deg+1);  xn = x*dinv;  agg init = xn (layer-1 self loop)
__global__ void k_dinv_xn(const float* __restrict__ x) {
    int i = blockIdx.x * blockDim.x + threadIdx.x;
    if (i >= N_NODES) { cudaGridDependencySynchronize(); return; }
    float4 xv = reinterpret_cast<const float4*>(x)[i];   // independent input
    cudaGridDependencySynchronize();                     // wait for k_deg
    float di = rsqrtf((float)(g_deg[i] + 1));
    g_dinv[i] = di;
    float4 xn = make_float4(xv.x * di, xv.y * di, xv.z * di, xv.w * di);
    reinterpret_cast<float4*>(g_xn)[i]  = xn;
    reinterpret_cast<float4*>(g_agg)[i] = xn;
}

// K3: layer-1 edges: agg[dst] += xn[src]  (dst factor deferred)
__global__ void k_l1_edges(const int* __restrict__ src, const int* __restrict__ dst) {
    int i = blockIdx.x * blockDim.x + threadIdx.x;
    if (i >= N_EDGES / 4) { cudaGridDependencySynchronize(); return; }
    int4 s = reinterpret_cast<const int4*>(src)[i];      // independent inputs
    int4 d = reinterpret_cast<const int4*>(dst)[i];
    cudaGridDependencySynchronize();                     // wait for k_dinv_xn
    const float4* xv = reinterpret_cast<const float4*>(g_xn);

    float4 v0 = xv[s.x];
    float4 v1 = xv[s.y];
    float4 v2 = xv[s.z];
    float4 v3 = xv[s.w];
    red_add_v4(&g_agg[4 * d.x], v0.x, v0.y, v0.z, v0.w);
    red_add_v4(&g_agg[4 * d.y], v1.x, v1.y, v1.z, v1.w);
    red_add_v4(&g_agg[4 * d.z], v2.x, v2.y, v2.z, v2.w);
    red_add_v4(&g_agg[4 * d.w], v3.x, v3.y, v3.z, v3.w);
}

// K4: per-node transform.
//   a = dinv*agg (agg already contains self loop); h = relu(a@W1+b1);
//   t = h@W2; tn = t*dinv; out init = tn (layer-2 self loop pre-dst-scale)
__global__ void k_xform(const float* __restrict__ W1, const float* __restrict__ b1,
                        const float* __restrict__ W2,
                        float* __restrict__ out) {
    int v = blockIdx.x * blockDim.x + threadIdx.x;
    if (v >= N_NODES) { cudaGridDependencySynchronize(); return; }
    // Weights are kernel inputs (independent of prior kernels) — prefetch
    // happens naturally via L1/L2; the per-node data is dependent.
    cudaGridDependencySynchronize();                     // wait for k_l1_edges
    float di = g_dinv[v];
    float4 ag = reinterpret_cast<const float4*>(g_agg)[v];
    float a0 = ag.x * di;
    float a1 = ag.y * di;
    float a2 = ag.z * di;
    float a3 = ag.w * di;

    float t0 = 0.f, t1 = 0.f;
    #pragma unroll
    for (int j = 0; j < 16; j++) {
        float h = a0 * W1[j] + a1 * W1[16 + j] + a2 * W1[32 + j] + a3 * W1[48 + j] + b1[j];
        h = fmaxf(h, 0.f);
        t0 += h * W2[2 * j];
        t1 += h * W2[2 * j + 1];
    }
    float tn0 = t0 * di, tn1 = t1 * di;
    reinterpret_cast<float2*>(g_tn)[v] = make_float2(tn0, tn1);
    reinterpret_cast<float2*>(out)[v]  = make_float2(tn0, tn1);  // self-loop init
}

// K5: layer-2 edges: out[dst] += tn[src]  (dst factor deferred)
__global__ void k_l2_edges(const int* __restrict__ src, const int* __restrict__ dst,
                           float* __restrict__ out) {
    int i = blockIdx.x * blockDim.x + threadIdx.x;
    if (i >= N_EDGES / 4) { cudaGridDependencySynchronize(); return; }
    int4 s = reinterpret_cast<const int4*>(src)[i];      // independent inputs
    int4 d = reinterpret_cast<const int4*>(dst)[i];
    cudaGridDependencySynchronize();                     // wait for k_xform
    const float2* tv = reinterpret_cast<const float2*>(g_tn);

    float2 t0 = tv[s.x];
    float2 t1 = tv[s.y];
    float2 t2 = tv[s.z];
    float2 t3 = tv[s.w];
    red_add_v2(&out[2 * d.x], t0.x, t0.y);
    red_add_v2(&out[2 * d.y], t1.x, t1.y);
    red_add_v2(&out[2 * d.z], t2.x, t2.y);
    red_add_v2(&out[2 * d.w], t3.x, t3.y);
}

// K6: apply deferred dst factor + bias:  out = out*dinv + b2.
//     Also re-zero g_deg for the next call.
__global__ void k_finish(float* __restrict__ out, const float* __restrict__ b2) {
    int v = blockIdx.x * blockDim.x + threadIdx.x;
    if (v >= N_NODES) { cudaGridDependencySynchronize(); return; }
    cudaGridDependencySynchronize();                     // wait for k_l2_edges
    float di = g_dinv[v];
    float2 o = reinterpret_cast<float2*>(out)[v];
    reinterpret_cast<float2*>(out)[v] =
        make_float2(o.x * di + b2[0], o.y * di + b2[1]);
    g_deg[v] = 0;
}

// PDL launch helper: allow this kernel to begin dispatch while its stream
// predecessor drains; the kernel's own cudaGridDependencySynchronize()
// provides the ordering/visibility guarantee.
template <typename... Args>
static inline void launch_pdl(void (*kern)(Args...), int grid, int block, Args... args) {
    cudaLaunchConfig_t cfg = {};
    cfg.gridDim  = dim3(grid, 1, 1);
    cfg.blockDim = dim3(block, 1, 1);
    cudaLaunchAttribute attr[1];
    attr[0].id = cudaLaunchAttributeProgrammaticStreamSerialization;
    attr[0].val.programmaticStreamSerializationAllowed = 1;
    cfg.attrs = attr;
    cfg.numAttrs = 1;
    cudaLaunchKernelEx(&cfg, kern, args...);
}

extern "C" void kernel_launch(void* const* d_in, const int* in_sizes, int n_in,
                              void* d_out, int out_size) {
    const float* x   = (const float*)d_in[0];     // [N, 4]
    const int*   ei  = (const int*)  d_in[1];     // [2, E]
    const float* W1  = (const float*)d_in[2];     // [4, 16]
    const float* b1  = (const float*)d_in[3];     // [16]
    const float* W2  = (const float*)d_in[4];     // [16, 2]
    const float* b2  = (const float*)d_in[5];     // [2]
    float* out = (float*)d_out;                   // [N, 2]

    const int* src = ei;
    const int* dst = ei + N_EDGES;

    const int TB = 256;
    int nodeBlocks = (N_NODES + TB - 1) / TB;
    int edgeBlocks = (N_EDGES / 4 + TB - 1) / TB;

    launch_pdl(k_deg,      edgeBlocks, TB, dst);
    launch_pdl(k_dinv_xn,  nodeBlocks, TB, x);
    launch_pdl(k_l1_edges, edgeBlocks, TB, src, dst);
    launch_pdl(k_xform,    nodeBlocks, TB, W1, b1, W2, out);
    launch_pdl(k_l2_edges, edgeBlocks, TB, src, dst, out);
    launch_pdl(k_finish,   nodeBlocks, TB, out, b2);
}

// round 12
// speedup vs baseline: 1.0991x; 1.0008x over previous
#include <cuda_runtime.h>

#define N_NODES 100000
#define N_EDGES 3200000

// ---- persistent device scratch (no allocations allowed) ----
// g_deg is zero-initialized at module load; k_finish re-zeroes it every call.
__device__ int   g_deg [N_NODES];
__device__ float g_dinv[N_NODES];
__device__ float g_xn  [N_NODES * 4];   // x * dinv  (src-normalized features)
__device__ float g_agg [N_NODES * 4];   // layer-1 accumulator, init = xn (self loop)
__device__ float g_tn  [N_NODES * 2];   // t * dinv  (src-normalized layer-2 features)

// Vectorized no-return global reductions (one L2 message per 2/4 floats).
__device__ __forceinline__ void red_add_v4(float* p, float a, float b, float c, float d) {
    asm volatile("red.global.add.v4.f32 [%0], {%1,%2,%3,%4};"
                 :: "l"(p), "f"(a), "f"(b), "f"(c), "f"(d) : "memory");
}
__device__ __forceinline__ void red_add_v2(float* p, float a, float b) {
    asm volatile("red.global.add.v2.f32 [%0], {%1,%2};"
                 :: "l"(p), "f"(a), "f"(b) : "memory");
}
__device__ __forceinline__ void red_add_u32(int* p) {
    asm volatile("red.global.add.u32 [%0], 1;" :: "l"(p) : "memory");
}

// K1: degree of dst endpoints. Index stream read with __ldcs (evict-first:
// each line touched once; keep L1 capacity for the gather-resident arrays).
__global__ void k_deg(const int* __restrict__ dst) {
    int i = blockIdx.x * blockDim.x + threadIdx.x;
    if (i < N_EDGES / 4) {
        int4 d = __ldcs(&reinterpret_cast<const int4*>(dst)[i]);
        cudaGridDependencySynchronize();
        red_add_u32(&g_deg[d.x]);
        red_add_u32(&g_deg[d.y]);
        red_add_u32(&g_deg[d.z]);
        red_add_u32(&g_deg[d.w]);
    } else {
        cudaGridDependencySynchronize();
    }
}

// K2: dinv = rsqrt(deg+1);  xn = x*dinv;  agg init = xn (layer-1 self loop)
__global__ void k_dinv_xn(const float* __restrict__ x) {
    int i = blockIdx.x * blockDim.x + threadIdx.x;
    if (i >= N_NODES) { cudaGridDependencySynchronize(); return; }
    float4 xv = reinterpret_cast<const float4*>(x)[i];   // independent input
    cudaGridDependencySynchronize();                     // wait for k_deg
    float di = rsqrtf((float)(g_deg[i] + 1));
    g_dinv[i] = di;
    float4 xn = make_float4(xv.x * di, xv.y * di, xv.z * di, xv.w * di);
    reinterpret_cast<float4*>(g_xn)[i]  = xn;
    reinterpret_cast<float4*>(g_agg)[i] = xn;
}

// K3: layer-1 edges: agg[dst] += xn[src]  (dst factor deferred)
// Index streams evict-first; gathers use default caching (hot-node reuse).
__global__ void k_l1_edges(const int* __restrict__ src, const int* __restrict__ dst) {
    int i = blockIdx.x * blockDim.x + threadIdx.x;
    if (i >= N_EDGES / 4) { cudaGridDependencySynchronize(); return; }
    int4 s = __ldcs(&reinterpret_cast<const int4*>(src)[i]);  // independent inputs
    int4 d = __ldcs(&reinterpret_cast<const int4*>(dst)[i]);
    cudaGridDependencySynchronize();                     // wait for k_dinv_xn
    const float4* xv = reinterpret_cast<const float4*>(g_xn);

    float4 v0 = xv[s.x];
    float4 v1 = xv[s.y];
    float4 v2 = xv[s.z];
    float4 v3 = xv[s.w];
    red_add_v4(&g_agg[4 * d.x], v0.x, v0.y, v0.z, v0.w);
    red_add_v4(&g_agg[4 * d.y], v1.x, v1.y, v1.z, v1.w);
    red_add_v4(&g_agg[4 * d.z], v2.x, v2.y, v2.z, v2.w);
    red_add_v4(&g_agg[4 * d.w], v3.x, v3.y, v3.z, v3.w);
}

// K4: per-node transform.
//   a = dinv*agg (agg already contains self loop); h = relu(a@W1+b1);
//   t = h@W2; tn = t*dinv; out init = tn (layer-2 self loop pre-dst-scale)
__global__ void k_xform(const float* __restrict__ W1, const float* __restrict__ b1,
                        const float* __restrict__ W2,
                        float* __restrict__ out) {
    int v = blockIdx.x * blockDim.x + threadIdx.x;
    if (v >= N_NODES) { cudaGridDependencySynchronize(); return; }
    cudaGridDependencySynchronize();                     // wait for k_l1_edges
    float di = g_dinv[v];
    float4 ag = reinterpret_cast<const float4*>(g_agg)[v];
    float a0 = ag.x * di;
    float a1 = ag.y * di;
    float a2 = ag.z * di;
    float a3 = ag.w * di;

    float t0 = 0.f, t1 = 0.f;
    #pragma unroll
    for (int j = 0; j < 16; j++) {
        float h = a0 * W1[j] + a1 * W1[16 + j] + a2 * W1[32 + j] + a3 * W1[48 + j] + b1[j];
        h = fmaxf(h, 0.f);
        t0 += h * W2[2 * j];
        t1 += h * W2[2 * j + 1];
    }
    float tn0 = t0 * di, tn1 = t1 * di;
    reinterpret_cast<float2*>(g_tn)[v] = make_float2(tn0, tn1);
    reinterpret_cast<float2*>(out)[v]  = make_float2(tn0, tn1);  // self-loop init
}

// K5: layer-2 edges: out[dst] += tn[src]  (dst factor deferred)
__global__ void k_l2_edges(const int* __restrict__ src, const int* __restrict__ dst,
                           float* __restrict__ out) {
    int i = blockIdx.x * blockDim.x + threadIdx.x;
    if (i >= N_EDGES / 4) { cudaGridDependencySynchronize(); return; }
    int4 s = __ldcs(&reinterpret_cast<const int4*>(src)[i]);  // independent inputs
    int4 d = __ldcs(&reinterpret_cast<const int4*>(dst)[i]);
    cudaGridDependencySynchronize();                     // wait for k_xform
    const float2* tv = reinterpret_cast<const float2*>(g_tn);

    float2 t0 = tv[s.x];
    float2 t1 = tv[s.y];
    float2 t2 = tv[s.z];
    float2 t3 = tv[s.w];
    red_add_v2(&out[2 * d.x], t0.x, t0.y);
    red_add_v2(&out[2 * d.y], t1.x, t1.y);
    red_add_v2(&out[2 * d.z], t2.x, t2.y);
    red_add_v2(&out[2 * d.w], t3.x, t3.y);
}

// K6: apply deferred dst factor + bias:  out = out*dinv + b2.
//     Also re-zero g_deg for the next call.
__global__ void k_finish(float* __restrict__ out, const float* __restrict__ b2) {
    int v = blockIdx.x * blockDim.x + threadIdx.x;
    if (v >= N_NODES) { cudaGridDependencySynchronize(); return; }
    cudaGridDependencySynchronize();                     // wait for k_l2_edges
    float di = g_dinv[v];
    float2 o = reinterpret_cast<float2*>(out)[v];
    reinterpret_cast<float2*>(out)[v] =
        make_float2(o.x * di + b2[0], o.y * di + b2[1]);
    g_deg[v] = 0;
}

// PDL launch helper: allow this kernel to begin dispatch while its stream
// predecessor drains; the kernel's own cudaGridDependencySynchronize()
// provides the ordering/visibility guarantee.
template <typename... Args>
static inline void launch_pdl(void (*kern)(Args...), int grid, int block, Args... args) {
    cudaLaunchConfig_t cfg = {};
    cfg.gridDim  = dim3(grid, 1, 1);
    cfg.blockDim = dim3(block, 1, 1);
    cudaLaunchAttribute attr[1];
    attr[0].id = cudaLaunchAttributeProgrammaticStreamSerialization;
    attr[0].val.programmaticStreamSerializationAllowed = 1;
    cfg.attrs = attr;
    cfg.numAttrs = 1;
    cudaLaunchKernelEx(&cfg, kern, args...);
}

extern "C" void kernel_launch(void* const* d_in, const int* in_sizes, int n_in,
                              void* d_out, int out_size) {
    const float* x   = (const float*)d_in[0];     // [N, 4]
    const int*   ei  = (const int*)  d_in[1];     // [2, E]
    const float* W1  = (const float*)d_in[2];     // [4, 16]
    const float* b1  = (const float*)d_in[3];     // [16]
    const float* W2  = (const float*)d_in[4];     // [16, 2]
    const float* b2  = (const float*)d_in[5];     // [2]
    float* out = (float*)d_out;                   // [N, 2]

    const int* src = ei;
    const int* dst = ei + N_EDGES;

    const int TB = 256;
    int nodeBlocks = (N_NODES + TB - 1) / TB;
    int edgeBlocks = (N_EDGES / 4 + TB - 1) / TB;

    launch_pdl(k_deg,      edgeBlocks, TB, dst);
    launch_pdl(k_dinv_xn,  nodeBlocks, TB, x);
    launch_pdl(k_l1_edges, edgeBlocks, TB, src, dst);
    launch_pdl(k_xform,    nodeBlocks, TB, W1, b1, W2, out);
    launch_pdl(k_l2_edges, edgeBlocks, TB, src, dst, out);
    launch_pdl(k_finish,   nodeBlocks, TB, out, b2);
}